// round 3
// baseline (speedup 1.0000x reference)
#include <cuda_runtime.h>

// Problem constants
#define B_   32
#define L_   1024
#define K_   64
#define N_   8
#define BLK_ (B_*L_*K_)          // 2,097,152 samples
#define CHUNK_L 32
#define CHUNKS  (L_/CHUNK_L)

// Output layout (flat f32, reference tuple order)
#define OFF_VQ  0L
#define OFF_HQ  4194304L
#define OFF_EBD 37748736L
#define OFF_EBC 39845888L
#define OFF_WD  41943040L
#define OFF_WC  48234496L

#define RND_MAGIC 12582912.0f    // 1.5 * 2^23 : exact RNE round for |x| <= 8

typedef unsigned long long ull;

// Scratch (device globals: allocation-free)
__device__ float g_hp[BLK_];
__device__ float g_part[B_*CHUNKS*K_];
__device__ float g_avg[B_*K_];

// ---- packed f32x2 helpers (bitwise-exact dual fp32 ops) ----
__device__ __forceinline__ ull pack2(float x, float y) {
    ull r; asm("mov.b64 %0,{%1,%2};" : "=l"(r) : "f"(x), "f"(y)); return r;
}
__device__ __forceinline__ void unpack2(ull v, float& x, float& y) {
    asm("mov.b64 {%0,%1},%2;" : "=f"(x), "=f"(y) : "l"(v));
}
__device__ __forceinline__ ull ffma2(ull a, ull b, ull c) {
    ull d; asm("fma.rn.f32x2 %0,%1,%2,%3;" : "=l"(d) : "l"(a), "l"(b), "l"(c)); return d;
}

// ---------------------------------------------------------------------------
// Kernel A: h_power + deterministic partial sums over l-chunks
// ---------------------------------------------------------------------------
__global__ __launch_bounds__(256) void kA_hpower(const float* __restrict__ H) {
    const int bx    = blockIdx.x;
    const int b     = bx >> 5;
    const int chunk = bx & 31;
    const int tid   = threadIdx.x;
    const int k     = tid & 63;
    const int lsub  = tid >> 6;

    const float2* __restrict__ H2 = (const float2*)H;

    float partial = 0.0f;
#pragma unroll
    for (int r = 0; r < CHUNK_L/4; ++r) {
        const int l  = chunk*CHUNK_L + r*4 + lsub;
        const long bl = (long)b*L_ + l;
        float hp = 0.0f;
#pragma unroll
        for (int n = 0; n < N_; ++n) {
            float2 hv = H2[(bl*N_ + n)*K_ + k];
            hp = fmaf(hv.x, hv.x, fmaf(hv.y, hv.y, hp));
        }
        g_hp[bl*K_ + k] = hp;
        partial += hp;
    }

    __shared__ float sm[256];
    sm[tid] = partial;
    __syncthreads();
    if (tid < 64) {
        float s = (sm[tid] + sm[tid+64]) + (sm[tid+128] + sm[tid+192]);
        g_part[bx*64 + tid] = s;
    }
}

// ---------------------------------------------------------------------------
// Kernel B: finalize avg_power
// ---------------------------------------------------------------------------
__global__ void kB_avg() {
    int i = blockIdx.x*blockDim.x + threadIdx.x;
    if (i >= B_*K_) return;
    int b = i >> 6;
    int k = i & 63;
    float s = 0.0f;
#pragma unroll
    for (int c = 0; c < CHUNKS; ++c)
        s += g_part[(b*CHUNKS + c)*64 + k];
    g_avg[i] = s * (1.0f/1024.0f);
}

// ---------------------------------------------------------------------------
// lsq forward: round(clip(x*rs, Qn, Qp)) * s, exact RNE via magic constant.
// ---------------------------------------------------------------------------
__device__ __forceinline__ float lsqv(float x, float rs, float s, float qn, float qp) {
    float t = x * rs;
    t = fminf(fmaxf(t, qn), qp);
    t = __fadd_rn(__fadd_rn(t, RND_MAGIC), -RND_MAGIC);
    return t * s;
}

// Per-sample epilogue after argmax decisions are known.
__device__ __forceinline__ void epilogue(
    int gt, float2 vv, int ad, int ac, const float* sS,
    const float2* __restrict__ H2, float* __restrict__ out)
{
    const int  k  = gt & 63;
    const long bl = gt >> 6;
    const long g3 = (long)gt * 3;

    const bool  fd  = (ad != 0);
    const float sd  = (ad == 2) ? sS[1] : sS[0];
    const float rsd = (ad == 2) ? sS[5] : sS[4];
    const float qnd = (ad == 2) ? -8.0f : -2.0f;
    const float qpd = (ad == 2) ?  7.0f :  1.0f;

    const bool  fc  = (ac != 0);
    const float sc  = (ac == 2) ? sS[3] : sS[2];
    const float rsc = (ac == 2) ? sS[7] : sS[6];
    const float qnc = (ac == 2) ? -8.0f : -2.0f;
    const float qpc = (ac == 2) ?  7.0f :  1.0f;

    float2 vq;
    vq.x = fd ? lsqv(vv.x, rsd, sd, qnd, qpd) : 0.0f;
    vq.y = fd ? lsqv(vv.y, rsd, sd, qnd, qpd) : 0.0f;
    ((float2*)(out + OFF_VQ))[gt] = vq;

    out[OFF_EBD + gt] = (ad == 1) ? 4.0f  : ((ad == 2) ? 8.0f  : 0.0f);
    out[OFF_EBC + gt] = (ac == 1) ? 32.0f : ((ac == 2) ? 64.0f : 0.0f);

    out[OFF_WD + g3+0] = (ad == 0) ? 1.0f : 0.0f;
    out[OFF_WD + g3+1] = (ad == 1) ? 1.0f : 0.0f;
    out[OFF_WD + g3+2] = (ad == 2) ? 1.0f : 0.0f;
    out[OFF_WC + g3+0] = (ac == 0) ? 1.0f : 0.0f;
    out[OFF_WC + g3+1] = (ac == 1) ? 1.0f : 0.0f;
    out[OFF_WC + g3+2] = (ac == 2) ? 1.0f : 0.0f;

    float2* __restrict__ HQ2 = (float2*)(out + OFF_HQ);
#pragma unroll
    for (int n = 0; n < N_; ++n) {
        const long hidx = (bl*N_ + n)*K_ + k;
        float2 hv = H2[hidx];
        float2 hq;
        hq.x = fc ? lsqv(hv.x, rsc, sc, qnc, qpc) : 0.0f;
        hq.y = fc ? lsqv(hv.y, rsc, sc, qnc, qpc) : 0.0f;
        HQ2[hidx] = hq;
    }
}

// ---------------------------------------------------------------------------
// Kernel C: fused MLP (f32x2, 2 samples/thread) + dual argmax + quantize
// grid = BLK_/512, block = 256. Thread handles samples gt and gt+256.
// ---------------------------------------------------------------------------
__global__ __launch_bounds__(256, 1) void kC_main(
    const float* __restrict__ v,   const float* __restrict__ H,
    const float* __restrict__ snr, const float* __restrict__ gd,
    const float* __restrict__ gc,
    const float* __restrict__ W1,  const float* __restrict__ b1,
    const float* __restrict__ W2,  const float* __restrict__ b2,
    const float* __restrict__ Wd,  const float* __restrict__ bd,
    const float* __restrict__ Wc,  const float* __restrict__ bc,
    const float* __restrict__ p_s2d, const float* __restrict__ p_s4d,
    const float* __restrict__ p_s2c, const float* __restrict__ p_s4c,
    float* __restrict__ out)
{
    __shared__ __align__(16) ull   sW1[5*16];
    __shared__ __align__(16) ull   sW2[32*16];
    __shared__ __align__(16) float sWh[32*8];    // per i: d0 d1 d2 c0 c1 c2 0 0
    __shared__ __align__(16) float sb1[32];
    __shared__ __align__(16) float sb2[32];
    __shared__ float sbh[6];
    __shared__ float sS[8];

    const int tid = threadIdx.x;
    {
        float* w1f = (float*)sW1;
        for (int i = tid; i < 160;  i += 256) w1f[i] = W1[i];
        float* w2f = (float*)sW2;
        for (int i = tid; i < 1024; i += 256) w2f[i] = W2[i];
        if (tid < 32) {
            sb1[tid] = b1[tid];
            sb2[tid] = b2[tid];
            sWh[tid*8+0] = Wd[tid*3+0];
            sWh[tid*8+1] = Wd[tid*3+1];
            sWh[tid*8+2] = Wd[tid*3+2];
            sWh[tid*8+3] = Wc[tid*3+0];
            sWh[tid*8+4] = Wc[tid*3+1];
            sWh[tid*8+5] = Wc[tid*3+2];
            sWh[tid*8+6] = 0.0f;
            sWh[tid*8+7] = 0.0f;
        }
        if (tid < 6) sbh[tid] = (tid < 3) ? bd[tid] : bc[tid-3];
        if (tid == 0) {
            float a = *p_s2d, bq = *p_s4d, c = *p_s2c, d = *p_s4c;
            sS[0] = a;  sS[1] = bq;  sS[2] = c;  sS[3] = d;
            sS[4] = 1.0f/a; sS[5] = 1.0f/bq; sS[6] = 1.0f/c; sS[7] = 1.0f/d;
        }
    }
    __syncthreads();

    const int gt0 = blockIdx.x*512 + tid;
    const int gt1 = gt0 + 256;

    // ---- per-sample inputs ----
    const float2 vv0 = ((const float2*)v)[gt0];
    const float2 vv1 = ((const float2*)v)[gt1];
    const float  sn0 = snr[gt0], sn1 = snr[gt1];
    const float  hp0 = g_hp[gt0], hp1 = g_hp[gt1];
    const float  av0 = g_avg[((gt0 >> 16) << 6) | (gt0 & 63)];
    const float  av1 = g_avg[((gt1 >> 16) << 6) | (gt1 & 63)];

    float pinA[5] = { vv0.x, vv0.y, sn0, hp0, av0 };
    float pinB[5] = { vv1.x, vv1.y, sn1, hp1, av1 };

    // ---- layer 1: 5 -> 32 (f32x2), weights shared by both samples ----
    ull accA[16], accB[16];
    {
        const ull* bp = (const ull*)sb1;
#pragma unroll
        for (int j = 0; j < 16; ++j) { accA[j] = bp[j]; accB[j] = accA[j]; }
#pragma unroll
        for (int i = 0; i < 5; ++i) {
            ull xa = pack2(pinA[i], pinA[i]);
            ull xb = pack2(pinB[i], pinB[i]);
            const ulonglong2* wr = (const ulonglong2*)(sW1 + i*16);
#pragma unroll
            for (int j2 = 0; j2 < 8; ++j2) {
                ulonglong2 w = wr[j2];
                accA[j2*2+0] = ffma2(xa, w.x, accA[j2*2+0]);
                accA[j2*2+1] = ffma2(xa, w.y, accA[j2*2+1]);
                accB[j2*2+0] = ffma2(xb, w.x, accB[j2*2+0]);
                accB[j2*2+1] = ffma2(xb, w.y, accB[j2*2+1]);
            }
        }
    }
    float h1A[32], h1B[32];
#pragma unroll
    for (int j = 0; j < 16; ++j) {
        float a, b2v; unpack2(accA[j], a, b2v);
        h1A[2*j] = fmaxf(a, 0.0f); h1A[2*j+1] = fmaxf(b2v, 0.0f);
        unpack2(accB[j], a, b2v);
        h1B[2*j] = fmaxf(a, 0.0f); h1B[2*j+1] = fmaxf(b2v, 0.0f);
    }

    // ---- layer 2: 32 -> 32 (f32x2), weights shared ----
    {
        const ull* bp = (const ull*)sb2;
#pragma unroll
        for (int j = 0; j < 16; ++j) { accA[j] = bp[j]; accB[j] = accA[j]; }
#pragma unroll
        for (int i = 0; i < 32; ++i) {
            ull xa = pack2(h1A[i], h1A[i]);
            ull xb = pack2(h1B[i], h1B[i]);
            const ulonglong2* wr = (const ulonglong2*)(sW2 + i*16);
#pragma unroll
            for (int j2 = 0; j2 < 8; ++j2) {
                ulonglong2 w = wr[j2];
                accA[j2*2+0] = ffma2(xa, w.x, accA[j2*2+0]);
                accA[j2*2+1] = ffma2(xa, w.y, accA[j2*2+1]);
                accB[j2*2+0] = ffma2(xb, w.x, accB[j2*2+0]);
                accB[j2*2+1] = ffma2(xb, w.y, accB[j2*2+1]);
            }
        }
    }
    float h2A[32], h2B[32];
#pragma unroll
    for (int j = 0; j < 16; ++j) {
        float a, b2v; unpack2(accA[j], a, b2v);
        h2A[2*j] = fmaxf(a, 0.0f); h2A[2*j+1] = fmaxf(b2v, 0.0f);
        unpack2(accB[j], a, b2v);
        h2B[2*j] = fmaxf(a, 0.0f); h2B[2*j+1] = fmaxf(b2v, 0.0f);
    }

    // ---- heads: packed (d0,d1)(d2,c0)(c1,c2), weights shared ----
    ull pA0 = pack2(sbh[0], sbh[1]);
    ull pA1 = pack2(sbh[2], sbh[3]);
    ull pA2 = pack2(sbh[4], sbh[5]);
    ull pB0 = pA0, pB1 = pA1, pB2 = pA2;
    {
        const ulonglong2* whv = (const ulonglong2*)sWh;
        const ull*        whu = (const ull*)sWh;
#pragma unroll
        for (int i = 0; i < 32; ++i) {
            ull xa = pack2(h2A[i], h2A[i]);
            ull xb = pack2(h2B[i], h2B[i]);
            ulonglong2 wa = whv[i*2];
            ull wb = whu[i*4+2];
            pA0 = ffma2(xa, wa.x, pA0);
            pA1 = ffma2(xa, wa.y, pA1);
            pA2 = ffma2(xa, wb,   pA2);
            pB0 = ffma2(xb, wa.x, pB0);
            pB1 = ffma2(xb, wa.y, pB1);
            pB2 = ffma2(xb, wb,   pB2);
        }
    }

    const float2* __restrict__ H2 = (const float2*)H;

    // ---- sample 0: argmax + epilogue ----
    {
        float ld0, ld1, ld2, lc0, lc1, lc2;
        unpack2(pA0, ld0, ld1); unpack2(pA1, ld2, lc0); unpack2(pA2, lc1, lc2);
        const long g3 = (long)gt0 * 3;
        float a0 = ld0 + gd[g3+0], a1 = ld1 + gd[g3+1], a2 = ld2 + gd[g3+2];
        int ad = 0; { float best = a0; if (a1 > best) { best = a1; ad = 1; } if (a2 > best) { ad = 2; } }
        float c0 = lc0 + gc[g3+0], c1 = lc1 + gc[g3+1], c2 = lc2 + gc[g3+2];
        int ac = 0; { float best = c0; if (c1 > best) { best = c1; ac = 1; } if (c2 > best) { ac = 2; } }
        epilogue(gt0, vv0, ad, ac, sS, H2, out);
    }
    // ---- sample 1: argmax + epilogue ----
    {
        float ld0, ld1, ld2, lc0, lc1, lc2;
        unpack2(pB0, ld0, ld1); unpack2(pB1, ld2, lc0); unpack2(pB2, lc1, lc2);
        const long g3 = (long)gt1 * 3;
        float a0 = ld0 + gd[g3+0], a1 = ld1 + gd[g3+1], a2 = ld2 + gd[g3+2];
        int ad = 0; { float best = a0; if (a1 > best) { best = a1; ad = 1; } if (a2 > best) { ad = 2; } }
        float c0 = lc0 + gc[g3+0], c1 = lc1 + gc[g3+1], c2 = lc2 + gc[g3+2];
        int ac = 0; { float best = c0; if (c1 > best) { best = c1; ac = 1; } if (c2 > best) { ac = 2; } }
        epilogue(gt1, vv1, ad, ac, sS, H2, out);
    }
}

// ---------------------------------------------------------------------------
// Launch
// ---------------------------------------------------------------------------
extern "C" void kernel_launch(void* const* d_in, const int* in_sizes, int n_in,
                              void* d_out, int out_size) {
    const float* v   = (const float*)d_in[0];
    const float* H   = (const float*)d_in[1];
    const float* snr = (const float*)d_in[2];
    const float* gd  = (const float*)d_in[3];
    const float* gc  = (const float*)d_in[4];
    const float* W1  = (const float*)d_in[5];
    const float* b1  = (const float*)d_in[6];
    const float* W2  = (const float*)d_in[7];
    const float* b2  = (const float*)d_in[8];
    const float* Wd  = (const float*)d_in[9];
    const float* bd  = (const float*)d_in[10];
    const float* Wc  = (const float*)d_in[11];
    const float* bc  = (const float*)d_in[12];
    const float* s2d = (const float*)d_in[13];
    const float* s4d = (const float*)d_in[14];
    const float* s2c = (const float*)d_in[15];
    const float* s4c = (const float*)d_in[16];
    float* out = (float*)d_out;

    kA_hpower<<<B_*CHUNKS, 256>>>(H);
    kB_avg<<<(B_*K_ + 255)/256, 256>>>();
    kC_main<<<BLK_/512, 256>>>(v, H, snr, gd, gc,
                               W1, b1, W2, b2, Wd, bd, Wc, bc,
                               s2d, s4d, s2c, s4c, out);
}

// round 4
// speedup vs baseline: 1.0299x; 1.0299x over previous
#include <cuda_runtime.h>

// Problem constants
#define B_   32
#define L_   1024
#define K_   64
#define N_   8
#define BLK_ (B_*L_*K_)          // 2,097,152 samples
#define CHUNK_L 32
#define CHUNKS  (L_/CHUNK_L)
#define NPART   (B_*CHUNKS)      // 1024 partial blocks

// Output layout (flat f32, reference tuple order)
#define OFF_VQ  0L
#define OFF_HQ  4194304L
#define OFF_EBD 37748736L
#define OFF_EBC 39845888L
#define OFF_WD  41943040L
#define OFF_WC  48234496L

#define RND_MAGIC 12582912.0f    // 1.5 * 2^23 : exact RNE round for |x| <= 8

typedef unsigned long long ull;

// Scratch (device globals: allocation-free)
__device__ float    g_part[NPART*K_];
__device__ float    g_avg[B_*K_];
__device__ unsigned g_ctr;       // zero-initialized; self-resetting

// ---- packed f32x2 helpers (bitwise-exact dual fp32 ops) ----
__device__ __forceinline__ ull pack2(float x, float y) {
    ull r; asm("mov.b64 %0,{%1,%2};" : "=l"(r) : "f"(x), "f"(y)); return r;
}
__device__ __forceinline__ void unpack2(ull v, float& x, float& y) {
    asm("mov.b64 {%0,%1},%2;" : "=f"(x), "=f"(y) : "l"(v));
}
__device__ __forceinline__ ull ffma2(ull a, ull b, ull c) {
    ull d; asm("fma.rn.f32x2 %0,%1,%2,%3;" : "=l"(d) : "l"(a), "l"(b), "l"(c)); return d;
}

// ---------------------------------------------------------------------------
// Kernel A: avg_power only (h_power recomputed in kC from its own H loads).
// Last block (atomic ticket) finalizes g_avg. Deterministic fixed-order sums.
// ---------------------------------------------------------------------------
__global__ __launch_bounds__(256) void kA_avg(const float* __restrict__ H) {
    const int bx    = blockIdx.x;
    const int b     = bx >> 5;
    const int chunk = bx & 31;
    const int tid   = threadIdx.x;
    const int k     = tid & 63;
    const int lsub  = tid >> 6;

    const float2* __restrict__ H2 = (const float2*)H;

    float partial = 0.0f;
#pragma unroll
    for (int r = 0; r < CHUNK_L/4; ++r) {
        const int l  = chunk*CHUNK_L + r*4 + lsub;
        const long bl = (long)b*L_ + l;
        float hp = 0.0f;
#pragma unroll
        for (int n = 0; n < N_; ++n) {
            float2 hv = H2[(bl*N_ + n)*K_ + k];
            hp = fmaf(hv.x, hv.x, fmaf(hv.y, hv.y, hp));
        }
        partial += hp;
    }

    __shared__ float sm[256];
    __shared__ unsigned s_ticket;
    sm[tid] = partial;
    __syncthreads();
    if (tid < 64) {
        float s = (sm[tid] + sm[tid+64]) + (sm[tid+128] + sm[tid+192]);
        g_part[bx*64 + tid] = s;
    }
    __threadfence();
    __syncthreads();
    if (tid == 0) s_ticket = atomicAdd(&g_ctr, 1u);
    __syncthreads();

    if (s_ticket == NPART - 1) {
        // last block: finalize all B_*K_ = 2048 averages
        for (int i = tid; i < B_*K_; i += 256) {
            const int bb = i >> 6;
            const int kk = i & 63;
            float s = 0.0f;
#pragma unroll
            for (int c = 0; c < CHUNKS; ++c)
                s += g_part[(bb*CHUNKS + c)*64 + kk];
            g_avg[i] = s * (1.0f/1024.0f);
        }
        if (tid == 0) g_ctr = 0;   // reset for next graph replay
    }
}

// ---------------------------------------------------------------------------
// lsq forward: round(clip(x*rs, Qn, Qp)) * s, exact RNE via magic constant.
// ---------------------------------------------------------------------------
__device__ __forceinline__ float lsqv(float x, float rs, float s, float qn, float qp) {
    float t = x * rs;
    t = fminf(fmaxf(t, qn), qp);
    t = __fadd_rn(__fadd_rn(t, RND_MAGIC), -RND_MAGIC);
    return t * s;
}

// ---------------------------------------------------------------------------
// Kernel C: prefetch globals -> inline h_power -> MLP (f32x2) -> argmax ->
// quantize from registers. One sample per thread.
// ---------------------------------------------------------------------------
__global__ __launch_bounds__(256) void kC_main(
    const float* __restrict__ v,   const float* __restrict__ H,
    const float* __restrict__ snr, const float* __restrict__ gd,
    const float* __restrict__ gc,
    const float* __restrict__ W1,  const float* __restrict__ b1,
    const float* __restrict__ W2,  const float* __restrict__ b2,
    const float* __restrict__ Wd,  const float* __restrict__ bd,
    const float* __restrict__ Wc,  const float* __restrict__ bc,
    const float* __restrict__ p_s2d, const float* __restrict__ p_s4d,
    const float* __restrict__ p_s2c, const float* __restrict__ p_s4c,
    float* __restrict__ out)
{
    __shared__ __align__(16) ull   sW1[5*16];
    __shared__ __align__(16) ull   sW2[32*16];
    __shared__ __align__(16) float sWh[32*8];    // per i: d0 d1 d2 c0 c1 c2 0 0
    __shared__ __align__(16) float sb1[32];
    __shared__ __align__(16) float sb2[32];
    __shared__ float sbh[6];
    __shared__ float sS[8];

    const int tid = threadIdx.x;
    {
        float* w1f = (float*)sW1;
        for (int i = tid; i < 160;  i += 256) w1f[i] = W1[i];
        float* w2f = (float*)sW2;
        for (int i = tid; i < 1024; i += 256) w2f[i] = W2[i];
        if (tid < 32) {
            sb1[tid] = b1[tid];
            sb2[tid] = b2[tid];
            sWh[tid*8+0] = Wd[tid*3+0];
            sWh[tid*8+1] = Wd[tid*3+1];
            sWh[tid*8+2] = Wd[tid*3+2];
            sWh[tid*8+3] = Wc[tid*3+0];
            sWh[tid*8+4] = Wc[tid*3+1];
            sWh[tid*8+5] = Wc[tid*3+2];
            sWh[tid*8+6] = 0.0f;
            sWh[tid*8+7] = 0.0f;
        }
        if (tid < 6) sbh[tid] = (tid < 3) ? bd[tid] : bc[tid-3];
        if (tid == 0) {
            float a = *p_s2d, bq = *p_s4d, c = *p_s2c, d = *p_s4c;
            sS[0] = a;  sS[1] = bq;  sS[2] = c;  sS[3] = d;
            sS[4] = 1.0f/a; sS[5] = 1.0f/bq; sS[6] = 1.0f/c; sS[7] = 1.0f/d;
        }
    }

    const int  gt = blockIdx.x*256 + tid;
    const int  k  = gt & 63;
    const long bl = gt >> 6;
    const int  b  = gt >> 16;
    const long g3 = (long)gt * 3;

    // ---- prefetch ALL per-sample globals (latency hidden under MLP) ----
    const float2* __restrict__ H2 = (const float2*)H;
    const long hbase = bl*(N_*K_) + k;
    float2 hr[N_];
#pragma unroll
    for (int n = 0; n < N_; ++n) hr[n] = H2[hbase + n*K_];

    const float2 vv   = ((const float2*)v)[gt];
    const float  snrv = snr[gt];
    const float  gd0 = gd[g3+0], gd1 = gd[g3+1], gd2 = gd[g3+2];
    const float  gc0 = gc[g3+0], gc1 = gc[g3+1], gc2 = gc[g3+2];
    const float  avgv = g_avg[(b<<6) | k];

    __syncthreads();   // smem weights ready

    // ---- h_power inline (identical fmaf ordering as before) ----
    float hpv = 0.0f;
#pragma unroll
    for (int n = 0; n < N_; ++n)
        hpv = fmaf(hr[n].x, hr[n].x, fmaf(hr[n].y, hr[n].y, hpv));

    float pin[5] = { vv.x, vv.y, snrv, hpv, avgv };

    // ---- layer 1: 5 -> 32 (f32x2), relu ----
    ull acc[16];
    {
        const ull* bp = (const ull*)sb1;
#pragma unroll
        for (int j = 0; j < 16; ++j) acc[j] = bp[j];
#pragma unroll
        for (int i = 0; i < 5; ++i) {
            ull xx = pack2(pin[i], pin[i]);
            const ulonglong2* wr = (const ulonglong2*)(sW1 + i*16);
#pragma unroll
            for (int j2 = 0; j2 < 8; ++j2) {
                ulonglong2 w = wr[j2];
                acc[j2*2+0] = ffma2(xx, w.x, acc[j2*2+0]);
                acc[j2*2+1] = ffma2(xx, w.y, acc[j2*2+1]);
            }
        }
    }
    float h1[32];
#pragma unroll
    for (int j = 0; j < 16; ++j) {
        float a, bq; unpack2(acc[j], a, bq);
        h1[2*j]   = fmaxf(a, 0.0f);
        h1[2*j+1] = fmaxf(bq, 0.0f);
    }

    // ---- layer 2: 32 -> 32 (f32x2), relu ----
    {
        const ull* bp = (const ull*)sb2;
#pragma unroll
        for (int j = 0; j < 16; ++j) acc[j] = bp[j];
#pragma unroll
        for (int i = 0; i < 32; ++i) {
            ull xx = pack2(h1[i], h1[i]);
            const ulonglong2* wr = (const ulonglong2*)(sW2 + i*16);
#pragma unroll
            for (int j2 = 0; j2 < 8; ++j2) {
                ulonglong2 w = wr[j2];
                acc[j2*2+0] = ffma2(xx, w.x, acc[j2*2+0]);
                acc[j2*2+1] = ffma2(xx, w.y, acc[j2*2+1]);
            }
        }
    }
    float h2[32];
#pragma unroll
    for (int j = 0; j < 16; ++j) {
        float a, bq; unpack2(acc[j], a, bq);
        h2[2*j]   = fmaxf(a, 0.0f);
        h2[2*j+1] = fmaxf(bq, 0.0f);
    }

    // ---- heads: packed (d0,d1)(d2,c0)(c1,c2) ----
    ull p0 = pack2(sbh[0], sbh[1]);
    ull p1 = pack2(sbh[2], sbh[3]);
    ull p2 = pack2(sbh[4], sbh[5]);
    {
        const ulonglong2* whv = (const ulonglong2*)sWh;
        const ull*        whu = (const ull*)sWh;
#pragma unroll
        for (int i = 0; i < 32; ++i) {
            ull xx = pack2(h2[i], h2[i]);
            ulonglong2 wa = whv[i*2];
            ull wb = whu[i*4+2];
            p0 = ffma2(xx, wa.x, p0);
            p1 = ffma2(xx, wa.y, p1);
            p2 = ffma2(xx, wb,   p2);
        }
    }
    float ld0, ld1, ld2, lc0, lc1, lc2;
    unpack2(p0, ld0, ld1);
    unpack2(p1, ld2, lc0);
    unpack2(p2, lc1, lc2);

    // ---- gumbel argmax (gumbels already in registers) ----
    float a0 = ld0 + gd0, a1 = ld1 + gd1, a2 = ld2 + gd2;
    int ad = 0; { float best = a0; if (a1 > best) { best = a1; ad = 1; } if (a2 > best) { ad = 2; } }
    float c0 = lc0 + gc0, c1 = lc1 + gc1, c2 = lc2 + gc2;
    int ac = 0; { float best = c0; if (c1 > best) { best = c1; ac = 1; } if (c2 > best) { ac = 2; } }

    // ---- quantizer parameter selection (exact vs one-hot weighted sum) ----
    const bool  fd  = (ad != 0);
    const float sd  = (ad == 2) ? sS[1] : sS[0];
    const float rsd = (ad == 2) ? sS[5] : sS[4];
    const float qnd = (ad == 2) ? -8.0f : -2.0f;
    const float qpd = (ad == 2) ?  7.0f :  1.0f;

    const bool  fc  = (ac != 0);
    const float sc  = (ac == 2) ? sS[3] : sS[2];
    const float rsc = (ac == 2) ? sS[7] : sS[6];
    const float qnc = (ac == 2) ? -8.0f : -2.0f;
    const float qpc = (ac == 2) ?  7.0f :  1.0f;

    // ---- H_q from prefetched registers (no reload) ----
    float2* __restrict__ HQ2 = (float2*)(out + OFF_HQ);
#pragma unroll
    for (int n = 0; n < N_; ++n) {
        float2 hq;
        hq.x = fc ? lsqv(hr[n].x, rsc, sc, qnc, qpc) : 0.0f;
        hq.y = fc ? lsqv(hr[n].y, rsc, sc, qnc, qpc) : 0.0f;
        HQ2[hbase + n*K_] = hq;
    }

    // ---- v_q ----
    {
        float2 vq;
        vq.x = fd ? lsqv(vv.x, rsd, sd, qnd, qpd) : 0.0f;
        vq.y = fd ? lsqv(vv.y, rsd, sd, qnd, qpd) : 0.0f;
        ((float2*)(out + OFF_VQ))[gt] = vq;
    }

    // ---- expected bits ----
    out[OFF_EBD + gt] = (ad == 1) ? 4.0f  : ((ad == 2) ? 8.0f  : 0.0f);
    out[OFF_EBC + gt] = (ac == 1) ? 32.0f : ((ac == 2) ? 64.0f : 0.0f);

    // ---- one-hots ----
    out[OFF_WD + g3+0] = (ad == 0) ? 1.0f : 0.0f;
    out[OFF_WD + g3+1] = (ad == 1) ? 1.0f : 0.0f;
    out[OFF_WD + g3+2] = (ad == 2) ? 1.0f : 0.0f;
    out[OFF_WC + g3+0] = (ac == 0) ? 1.0f : 0.0f;
    out[OFF_WC + g3+1] = (ac == 1) ? 1.0f : 0.0f;
    out[OFF_WC + g3+2] = (ac == 2) ? 1.0f : 0.0f;
}

// ---------------------------------------------------------------------------
// Launch
// ---------------------------------------------------------------------------
extern "C" void kernel_launch(void* const* d_in, const int* in_sizes, int n_in,
                              void* d_out, int out_size) {
    const float* v   = (const float*)d_in[0];
    const float* H   = (const float*)d_in[1];
    const float* snr = (const float*)d_in[2];
    const float* gd  = (const float*)d_in[3];
    const float* gc  = (const float*)d_in[4];
    const float* W1  = (const float*)d_in[5];
    const float* b1  = (const float*)d_in[6];
    const float* W2  = (const float*)d_in[7];
    const float* b2  = (const float*)d_in[8];
    const float* Wd  = (const float*)d_in[9];
    const float* bd  = (const float*)d_in[10];
    const float* Wc  = (const float*)d_in[11];
    const float* bc  = (const float*)d_in[12];
    const float* s2d = (const float*)d_in[13];
    const float* s4d = (const float*)d_in[14];
    const float* s2c = (const float*)d_in[15];
    const float* s4c = (const float*)d_in[16];
    float* out = (float*)d_out;

    kA_avg<<<NPART, 256>>>(H);
    kC_main<<<BLK_/256, 256>>>(v, H, snr, gd, gc,
                               W1, b1, W2, b2, Wd, bd, Wc, bc,
                               s2d, s4d, s2c, s4c, out);
}

// round 5
// speedup vs baseline: 1.4042x; 1.3634x over previous
#include <cuda_runtime.h>

// Problem constants
#define B_   32
#define L_   1024
#define K_   64
#define N_   8
#define BLK_ (B_*L_*K_)          // 2,097,152 samples
#define CHUNK_L 32
#define CHUNKS  (L_/CHUNK_L)
#define NPART   (B_*CHUNKS)

// Output layout (flat f32, reference tuple order)
#define OFF_VQ  0L
#define OFF_HQ  4194304L
#define OFF_EBD 37748736L
#define OFF_EBC 39845888L
#define OFF_WD  41943040L
#define OFF_WC  48234496L

#define RND_MAGIC 12582912.0f    // 1.5 * 2^23 : exact RNE round for |x| <= 8

typedef unsigned long long ull;

// Scratch (device globals: allocation-free)
__device__ float    g_part[NPART*K_];
__device__ float    g_avg[B_*K_];
__device__ unsigned g_ctr;
__device__ __align__(16) float g_wh[32*8];   // interleaved head weights
__device__ __align__(16) float g_bs[16];     // head biases + scales/recips

// Constant-bank weights (read via the uniform-constant port, NOT L1)
__constant__ __align__(16) float cW1[5*32];
__constant__ __align__(16) float cW2[32*32];
__constant__ __align__(16) float cWh[32*8];  // per i: d0 d1 d2 c0 c1 c2 0 0
__constant__ __align__(16) float cb1[32];
__constant__ __align__(16) float cb2[32];
__constant__ __align__(16) float cBS[16];    // [0..5]=bd,bc  [8..15]=s2d s4d s2c s4c r2d r4d r2c r4c

// ---- packed f32x2 helpers (bitwise-exact dual fp32 ops) ----
__device__ __forceinline__ ull pack2(float x, float y) {
    ull r; asm("mov.b64 %0,{%1,%2};" : "=l"(r) : "f"(x), "f"(y)); return r;
}
__device__ __forceinline__ void unpack2(ull v, float& x, float& y) {
    asm("mov.b64 {%0,%1},%2;" : "=f"(x), "=f"(y) : "l"(v));
}
__device__ __forceinline__ ull ffma2(ull a, ull b, ull c) {
    ull d; asm("fma.rn.f32x2 %0,%1,%2,%3;" : "=l"(d) : "l"(a), "l"(b), "l"(c)); return d;
}

// ---------------------------------------------------------------------------
// Kernel P: build interleaved head-weight table + scales (tiny, once/replay)
// ---------------------------------------------------------------------------
__global__ void kP_prep(const float* __restrict__ Wd, const float* __restrict__ Wc,
                        const float* __restrict__ bd, const float* __restrict__ bc,
                        const float* __restrict__ s2d, const float* __restrict__ s4d,
                        const float* __restrict__ s2c, const float* __restrict__ s4c) {
    const int tid = threadIdx.x;
    if (tid < 32) {
        g_wh[tid*8+0] = Wd[tid*3+0];
        g_wh[tid*8+1] = Wd[tid*3+1];
        g_wh[tid*8+2] = Wd[tid*3+2];
        g_wh[tid*8+3] = Wc[tid*3+0];
        g_wh[tid*8+4] = Wc[tid*3+1];
        g_wh[tid*8+5] = Wc[tid*3+2];
        g_wh[tid*8+6] = 0.0f;
        g_wh[tid*8+7] = 0.0f;
    }
    if (tid == 0) {
        g_bs[0] = bd[0]; g_bs[1] = bd[1]; g_bs[2] = bd[2];
        g_bs[3] = bc[0]; g_bs[4] = bc[1]; g_bs[5] = bc[2];
        g_bs[6] = 0.0f;  g_bs[7] = 0.0f;
        float a = *s2d, bq = *s4d, c = *s2c, d = *s4c;
        g_bs[8]  = a;       g_bs[9]  = bq;      g_bs[10] = c;       g_bs[11] = d;
        g_bs[12] = 1.0f/a;  g_bs[13] = 1.0f/bq; g_bs[14] = 1.0f/c;  g_bs[15] = 1.0f/d;
    }
}

// ---------------------------------------------------------------------------
// Kernel A: avg_power (ticket-based last-block finalize; deterministic order)
// ---------------------------------------------------------------------------
__global__ __launch_bounds__(256) void kA_avg(const float* __restrict__ H) {
    const int bx    = blockIdx.x;
    const int b     = bx >> 5;
    const int chunk = bx & 31;
    const int tid   = threadIdx.x;
    const int k     = tid & 63;
    const int lsub  = tid >> 6;

    const float2* __restrict__ H2 = (const float2*)H;

    float partial = 0.0f;
#pragma unroll
    for (int r = 0; r < CHUNK_L/4; ++r) {
        const int l  = chunk*CHUNK_L + r*4 + lsub;
        const long bl = (long)b*L_ + l;
        float hp = 0.0f;
#pragma unroll
        for (int n = 0; n < N_; ++n) {
            float2 hv = H2[(bl*N_ + n)*K_ + k];
            hp = fmaf(hv.x, hv.x, fmaf(hv.y, hv.y, hp));
        }
        partial += hp;
    }

    __shared__ float sm[256];
    __shared__ unsigned s_ticket;
    sm[tid] = partial;
    __syncthreads();
    if (tid < 64) {
        float s = (sm[tid] + sm[tid+64]) + (sm[tid+128] + sm[tid+192]);
        g_part[bx*64 + tid] = s;
    }
    __threadfence();
    __syncthreads();
    if (tid == 0) s_ticket = atomicAdd(&g_ctr, 1u);
    __syncthreads();

    if (s_ticket == NPART - 1) {
        for (int i = tid; i < B_*K_; i += 256) {
            const int bb = i >> 6;
            const int kk = i & 63;
            float s = 0.0f;
#pragma unroll
            for (int c = 0; c < CHUNKS; ++c)
                s += g_part[(bb*CHUNKS + c)*64 + kk];
            g_avg[i] = s * (1.0f/1024.0f);
        }
        if (tid == 0) g_ctr = 0;
    }
}

// ---------------------------------------------------------------------------
// lsq forward: round(clip(x*rs, Qn, Qp)) * s, exact RNE via magic constant.
// ---------------------------------------------------------------------------
__device__ __forceinline__ float lsqv(float x, float rs, float s, float qn, float qp) {
    float t = x * rs;
    t = fminf(fmaxf(t, qn), qp);
    t = __fadd_rn(__fadd_rn(t, RND_MAGIC), -RND_MAGIC);
    return t * s;
}

// ---------------------------------------------------------------------------
// Kernel C: MLP with constant-bank weights (uniform port), no shared memory.
// ---------------------------------------------------------------------------
__global__ __launch_bounds__(256) void kC_main(
    const float* __restrict__ v,   const float* __restrict__ H,
    const float* __restrict__ snr, const float* __restrict__ gd,
    const float* __restrict__ gc,  float* __restrict__ out)
{
    const int tid = threadIdx.x;
    const int gt  = blockIdx.x*256 + tid;
    const int k   = gt & 63;
    const long bl = gt >> 6;
    const int  b  = gt >> 16;
    const long g3 = (long)gt * 3;

    // ---- prefetch per-sample globals (latency hides under MLP) ----
    const float2* __restrict__ H2 = (const float2*)H;
    const long hbase = bl*(N_*K_) + k;
    float2 hr[N_];
#pragma unroll
    for (int n = 0; n < N_; ++n) hr[n] = H2[hbase + n*K_];

    const float2 vv   = ((const float2*)v)[gt];
    const float  snrv = snr[gt];
    const float  gd0 = gd[g3+0], gd1 = gd[g3+1], gd2 = gd[g3+2];
    const float  gc0 = gc[g3+0], gc1 = gc[g3+1], gc2 = gc[g3+2];
    const float  avgv = g_avg[(b<<6) | k];

    // ---- h_power inline (same fmaf order as reference path) ----
    float hpv = 0.0f;
#pragma unroll
    for (int n = 0; n < N_; ++n)
        hpv = fmaf(hr[n].x, hr[n].x, fmaf(hr[n].y, hr[n].y, hpv));

    float pin[5] = { vv.x, vv.y, snrv, hpv, avgv };

    // ---- layer 1: 5 -> 32 (f32x2), weights from constant bank ----
    ull acc[16];
    {
        const ull* bp = (const ull*)cb1;
#pragma unroll
        for (int j = 0; j < 16; ++j) acc[j] = bp[j];
#pragma unroll
        for (int i = 0; i < 5; ++i) {
            ull xx = pack2(pin[i], pin[i]);
            const ulonglong2* wr = (const ulonglong2*)(cW1 + i*32);
#pragma unroll
            for (int j2 = 0; j2 < 8; ++j2) {
                ulonglong2 w = wr[j2];
                acc[j2*2+0] = ffma2(xx, w.x, acc[j2*2+0]);
                acc[j2*2+1] = ffma2(xx, w.y, acc[j2*2+1]);
            }
        }
    }
    float h1[32];
#pragma unroll
    for (int j = 0; j < 16; ++j) {
        float a, bq; unpack2(acc[j], a, bq);
        h1[2*j]   = fmaxf(a, 0.0f);
        h1[2*j+1] = fmaxf(bq, 0.0f);
    }

    // ---- layer 2: 32 -> 32 (f32x2), weights from constant bank ----
    {
        const ull* bp = (const ull*)cb2;
#pragma unroll
        for (int j = 0; j < 16; ++j) acc[j] = bp[j];
#pragma unroll
        for (int i = 0; i < 32; ++i) {
            ull xx = pack2(h1[i], h1[i]);
            const ulonglong2* wr = (const ulonglong2*)(cW2 + i*32);
#pragma unroll
            for (int j2 = 0; j2 < 8; ++j2) {
                ulonglong2 w = wr[j2];
                acc[j2*2+0] = ffma2(xx, w.x, acc[j2*2+0]);
                acc[j2*2+1] = ffma2(xx, w.y, acc[j2*2+1]);
            }
        }
    }
    float h2[32];
#pragma unroll
    for (int j = 0; j < 16; ++j) {
        float a, bq; unpack2(acc[j], a, bq);
        h2[2*j]   = fmaxf(a, 0.0f);
        h2[2*j+1] = fmaxf(bq, 0.0f);
    }

    // ---- heads: packed (d0,d1)(d2,c0)(c1,c2), weights from constant bank ----
    ull p0 = pack2(cBS[0], cBS[1]);
    ull p1 = pack2(cBS[2], cBS[3]);
    ull p2 = pack2(cBS[4], cBS[5]);
    {
#pragma unroll
        for (int i = 0; i < 32; ++i) {
            ull xx = pack2(h2[i], h2[i]);
            const ulonglong2* wa = (const ulonglong2*)(cWh + i*8);
            ulonglong2 w01 = wa[0];
            ull w2v = ((const ull*)(cWh + i*8))[2];
            p0 = ffma2(xx, w01.x, p0);
            p1 = ffma2(xx, w01.y, p1);
            p2 = ffma2(xx, w2v,   p2);
        }
    }
    float ld0, ld1, ld2, lc0, lc1, lc2;
    unpack2(p0, ld0, ld1);
    unpack2(p1, ld2, lc0);
    unpack2(p2, lc1, lc2);

    // ---- gumbel argmax ----
    float a0 = ld0 + gd0, a1 = ld1 + gd1, a2 = ld2 + gd2;
    int ad = 0; { float best = a0; if (a1 > best) { best = a1; ad = 1; } if (a2 > best) { ad = 2; } }
    float c0 = lc0 + gc0, c1 = lc1 + gc1, c2 = lc2 + gc2;
    int ac = 0; { float best = c0; if (c1 > best) { best = c1; ac = 1; } if (c2 > best) { ac = 2; } }

    // ---- quantizer parameter selection (exact vs one-hot weighted sum) ----
    const bool  fd  = (ad != 0);
    const float sd  = (ad == 2) ? cBS[9]  : cBS[8];
    const float rsd = (ad == 2) ? cBS[13] : cBS[12];
    const float qnd = (ad == 2) ? -8.0f : -2.0f;
    const float qpd = (ad == 2) ?  7.0f :  1.0f;

    const bool  fc  = (ac != 0);
    const float sc  = (ac == 2) ? cBS[11] : cBS[10];
    const float rsc = (ac == 2) ? cBS[15] : cBS[14];
    const float qnc = (ac == 2) ? -8.0f : -2.0f;
    const float qpc = (ac == 2) ?  7.0f :  1.0f;

    // ---- H_q from prefetched registers ----
    float2* __restrict__ HQ2 = (float2*)(out + OFF_HQ);
#pragma unroll
    for (int n = 0; n < N_; ++n) {
        float2 hq;
        hq.x = fc ? lsqv(hr[n].x, rsc, sc, qnc, qpc) : 0.0f;
        hq.y = fc ? lsqv(hr[n].y, rsc, sc, qnc, qpc) : 0.0f;
        HQ2[hbase + n*K_] = hq;
    }

    // ---- v_q ----
    {
        float2 vq;
        vq.x = fd ? lsqv(vv.x, rsd, sd, qnd, qpd) : 0.0f;
        vq.y = fd ? lsqv(vv.y, rsd, sd, qnd, qpd) : 0.0f;
        ((float2*)(out + OFF_VQ))[gt] = vq;
    }

    // ---- expected bits ----
    out[OFF_EBD + gt] = (ad == 1) ? 4.0f  : ((ad == 2) ? 8.0f  : 0.0f);
    out[OFF_EBC + gt] = (ac == 1) ? 32.0f : ((ac == 2) ? 64.0f : 0.0f);

    // ---- one-hots ----
    out[OFF_WD + g3+0] = (ad == 0) ? 1.0f : 0.0f;
    out[OFF_WD + g3+1] = (ad == 1) ? 1.0f : 0.0f;
    out[OFF_WD + g3+2] = (ad == 2) ? 1.0f : 0.0f;
    out[OFF_WC + g3+0] = (ac == 0) ? 1.0f : 0.0f;
    out[OFF_WC + g3+1] = (ac == 1) ? 1.0f : 0.0f;
    out[OFF_WC + g3+2] = (ac == 2) ? 1.0f : 0.0f;
}

// ---------------------------------------------------------------------------
// Launch
// ---------------------------------------------------------------------------
extern "C" void kernel_launch(void* const* d_in, const int* in_sizes, int n_in,
                              void* d_out, int out_size) {
    const float* v   = (const float*)d_in[0];
    const float* H   = (const float*)d_in[1];
    const float* snr = (const float*)d_in[2];
    const float* gd  = (const float*)d_in[3];
    const float* gc  = (const float*)d_in[4];
    const float* W1  = (const float*)d_in[5];
    const float* b1  = (const float*)d_in[6];
    const float* W2  = (const float*)d_in[7];
    const float* b2  = (const float*)d_in[8];
    const float* Wd  = (const float*)d_in[9];
    const float* bd  = (const float*)d_in[10];
    const float* Wc  = (const float*)d_in[11];
    const float* bc  = (const float*)d_in[12];
    const float* s2d = (const float*)d_in[13];
    const float* s4d = (const float*)d_in[14];
    const float* s2c = (const float*)d_in[15];
    const float* s4c = (const float*)d_in[16];
    float* out = (float*)d_out;

    // Raw weight tables -> constant bank (D2D async memcpy nodes)
    cudaMemcpyToSymbolAsync(cW1, W1, 5*32*sizeof(float), 0, cudaMemcpyDeviceToDevice, 0);
    cudaMemcpyToSymbolAsync(cW2, W2, 32*32*sizeof(float), 0, cudaMemcpyDeviceToDevice, 0);
    cudaMemcpyToSymbolAsync(cb1, b1, 32*sizeof(float), 0, cudaMemcpyDeviceToDevice, 0);
    cudaMemcpyToSymbolAsync(cb2, b2, 32*sizeof(float), 0, cudaMemcpyDeviceToDevice, 0);

    // Derived tables: build in __device__ globals, then copy to constant
    kP_prep<<<1, 32>>>(Wd, Wc, bd, bc, s2d, s4d, s2c, s4c);
    void *p_wh = nullptr, *p_bs = nullptr;
    cudaGetSymbolAddress(&p_wh, g_wh);
    cudaGetSymbolAddress(&p_bs, g_bs);
    cudaMemcpyToSymbolAsync(cWh, p_wh, 32*8*sizeof(float), 0, cudaMemcpyDeviceToDevice, 0);
    cudaMemcpyToSymbolAsync(cBS, p_bs, 16*sizeof(float), 0, cudaMemcpyDeviceToDevice, 0);

    kA_avg<<<NPART, 256>>>(H);
    kC_main<<<BLK_/256, 256>>>(v, H, snr, gd, gc, out);
}

// round 6
// speedup vs baseline: 1.5339x; 1.0924x over previous
#include <cuda_runtime.h>

// Problem constants
#define B_   32
#define L_   1024
#define K_   64
#define N_   8
#define BLK_ (B_*L_*K_)          // 2,097,152 samples
#define CHUNK_L 32
#define CHUNKS  (L_/CHUNK_L)
#define NPART   (B_*CHUNKS)

// Output layout (flat f32, reference tuple order)
#define OFF_VQ  0L
#define OFF_HQ  4194304L
#define OFF_EBD 37748736L
#define OFF_EBC 39845888L
#define OFF_WD  41943040L
#define OFF_WC  48234496L

#define RND_MAGIC 12582912.0f    // 1.5 * 2^23 : exact RNE round for |x| <= 8

typedef unsigned long long ull;

// Scratch (device globals: allocation-free)
__device__ float    g_part[NPART*K_];
__device__ float    g_avg[B_*K_];
__device__ unsigned g_ctr;
__device__ __align__(16) float g_wh[32*8];   // interleaved head weights
__device__ __align__(16) float g_bs[16];     // head biases + scales/recips

// Constant-bank weights (uniform-constant port, not L1)
__constant__ __align__(16) float cW1[5*32];
__constant__ __align__(16) float cW2[32*32];
__constant__ __align__(16) float cWh[32*8];  // per i: d0 d1 d2 c0 c1 c2 0 0
__constant__ __align__(16) float cb1[32];
__constant__ __align__(16) float cb2[32];
__constant__ __align__(16) float cBS[16];    // [0..5]=bd,bc  [8..15]=s2d s4d s2c s4c r2d r4d r2c r4c

// ---- packed f32x2 helpers (bitwise-exact dual fp32 ops) ----
__device__ __forceinline__ ull pack2(float x, float y) {
    ull r; asm("mov.b64 %0,{%1,%2};" : "=l"(r) : "f"(x), "f"(y)); return r;
}
__device__ __forceinline__ void unpack2(ull v, float& x, float& y) {
    asm("mov.b64 {%0,%1},%2;" : "=f"(x), "=f"(y) : "l"(v));
}
__device__ __forceinline__ ull ffma2(ull a, ull b, ull c) {
    ull d; asm("fma.rn.f32x2 %0,%1,%2,%3;" : "=l"(d) : "l"(a), "l"(b), "l"(c)); return d;
}

// ---------------------------------------------------------------------------
// Kernel A: avg_power (ticket last-block finalize) + derived-table prep in
// block 0 (replaces the old kP_prep launch).
// ---------------------------------------------------------------------------
__global__ __launch_bounds__(256) void kA_avg(
    const float* __restrict__ H,
    const float* __restrict__ Wd, const float* __restrict__ Wc,
    const float* __restrict__ bd, const float* __restrict__ bc,
    const float* __restrict__ s2d, const float* __restrict__ s4d,
    const float* __restrict__ s2c, const float* __restrict__ s4c)
{
    const int bx    = blockIdx.x;
    const int tid   = threadIdx.x;

    // ---- block 0 prologue: build derived tables (visible at kernel end) ----
    if (bx == 0) {
        if (tid < 32) {
            g_wh[tid*8+0] = Wd[tid*3+0];
            g_wh[tid*8+1] = Wd[tid*3+1];
            g_wh[tid*8+2] = Wd[tid*3+2];
            g_wh[tid*8+3] = Wc[tid*3+0];
            g_wh[tid*8+4] = Wc[tid*3+1];
            g_wh[tid*8+5] = Wc[tid*3+2];
            g_wh[tid*8+6] = 0.0f;
            g_wh[tid*8+7] = 0.0f;
        }
        if (tid == 0) {
            g_bs[0] = bd[0]; g_bs[1] = bd[1]; g_bs[2] = bd[2];
            g_bs[3] = bc[0]; g_bs[4] = bc[1]; g_bs[5] = bc[2];
            g_bs[6] = 0.0f;  g_bs[7] = 0.0f;
            float a = *s2d, bq = *s4d, c = *s2c, d = *s4c;
            g_bs[8]  = a;       g_bs[9]  = bq;      g_bs[10] = c;       g_bs[11] = d;
            g_bs[12] = 1.0f/a;  g_bs[13] = 1.0f/bq; g_bs[14] = 1.0f/c;  g_bs[15] = 1.0f/d;
        }
    }

    const int b     = bx >> 5;
    const int chunk = bx & 31;
    const int k     = tid & 63;
    const int lsub  = tid >> 6;

    const float2* __restrict__ H2 = (const float2*)H;

    float partial = 0.0f;
#pragma unroll
    for (int r = 0; r < CHUNK_L/4; ++r) {
        const int l  = chunk*CHUNK_L + r*4 + lsub;
        const long bl = (long)b*L_ + l;
        float hp = 0.0f;
#pragma unroll
        for (int n = 0; n < N_; ++n) {
            float2 hv = H2[(bl*N_ + n)*K_ + k];
            hp = fmaf(hv.x, hv.x, fmaf(hv.y, hv.y, hp));
        }
        partial += hp;
    }

    __shared__ float sm[256];
    __shared__ unsigned s_ticket;
    sm[tid] = partial;
    __syncthreads();
    if (tid < 64) {
        float s = (sm[tid] + sm[tid+64]) + (sm[tid+128] + sm[tid+192]);
        g_part[bx*64 + tid] = s;
    }
    __threadfence();
    __syncthreads();
    if (tid == 0) s_ticket = atomicAdd(&g_ctr, 1u);
    __syncthreads();

    if (s_ticket == NPART - 1) {
        for (int i = tid; i < B_*K_; i += 256) {
            const int bb = i >> 6;
            const int kk = i & 63;
            float s = 0.0f;
#pragma unroll
            for (int c = 0; c < CHUNKS; ++c)
                s += g_part[(bb*CHUNKS + c)*64 + kk];
            g_avg[i] = s * (1.0f/1024.0f);
        }
        if (tid == 0) g_ctr = 0;
    }
}

// ---------------------------------------------------------------------------
// lsq forward: round(clip(x*rs, Qn, Qp)) * s, exact RNE via magic constant.
// ---------------------------------------------------------------------------
__device__ __forceinline__ float lsqv(float x, float rs, float s, float qn, float qp) {
    float t = x * rs;
    t = fminf(fmaxf(t, qn), qp);
    t = __fadd_rn(__fadd_rn(t, RND_MAGIC), -RND_MAGIC);
    return t * s;
}

// ---------------------------------------------------------------------------
// Kernel C: MLP (f32x2, constant weights). Register-lean: H consumed into
// h_power and RELOADED in epilogue (L2 hit); gd/gc loaded before layer 2.
// ---------------------------------------------------------------------------
__global__ __launch_bounds__(256, 3) void kC_main(
    const float* __restrict__ v,   const float* __restrict__ H,
    const float* __restrict__ snr, const float* __restrict__ gd,
    const float* __restrict__ gc,  float* __restrict__ out)
{
    const int tid = threadIdx.x;
    const int gt  = blockIdx.x*256 + tid;
    const int k   = gt & 63;
    const long bl = gt >> 6;
    const int  b  = gt >> 16;
    const long g3 = (long)gt * 3;

    const float2* __restrict__ H2 = (const float2*)H;
    const long hbase = bl*(N_*K_) + k;

    // ---- h_power: stream H through fma, registers die immediately ----
    float hpv = 0.0f;
#pragma unroll
    for (int n = 0; n < N_; ++n) {
        float2 hv = __ldg(&H2[hbase + n*K_]);
        hpv = fmaf(hv.x, hv.x, fmaf(hv.y, hv.y, hpv));
    }

    const float2 vv   = ((const float2*)v)[gt];
    const float  snrv = snr[gt];
    const float  avgv = g_avg[(b<<6) | k];

    float pin[5] = { vv.x, vv.y, snrv, hpv, avgv };

    // ---- layer 1: 5 -> 32 (f32x2) ----
    ull acc[16];
    {
        const ull* bp = (const ull*)cb1;
#pragma unroll
        for (int j = 0; j < 16; ++j) acc[j] = bp[j];
#pragma unroll
        for (int i = 0; i < 5; ++i) {
            ull xx = pack2(pin[i], pin[i]);
            const ulonglong2* wr = (const ulonglong2*)(cW1 + i*32);
#pragma unroll
            for (int j2 = 0; j2 < 8; ++j2) {
                ulonglong2 w = wr[j2];
                acc[j2*2+0] = ffma2(xx, w.x, acc[j2*2+0]);
                acc[j2*2+1] = ffma2(xx, w.y, acc[j2*2+1]);
            }
        }
    }
    float h1[32];
#pragma unroll
    for (int j = 0; j < 16; ++j) {
        float a, bq; unpack2(acc[j], a, bq);
        h1[2*j]   = fmaxf(a, 0.0f);
        h1[2*j+1] = fmaxf(bq, 0.0f);
    }

    // ---- issue gumbel loads here: ~500+ cycles of FMA ahead of use ----
    const float gd0 = __ldg(&gd[g3+0]), gd1 = __ldg(&gd[g3+1]), gd2 = __ldg(&gd[g3+2]);
    const float gc0 = __ldg(&gc[g3+0]), gc1 = __ldg(&gc[g3+1]), gc2 = __ldg(&gc[g3+2]);

    // ---- layer 2: 32 -> 32 (f32x2) ----
    {
        const ull* bp = (const ull*)cb2;
#pragma unroll
        for (int j = 0; j < 16; ++j) acc[j] = bp[j];
#pragma unroll
        for (int i = 0; i < 32; ++i) {
            ull xx = pack2(h1[i], h1[i]);
            const ulonglong2* wr = (const ulonglong2*)(cW2 + i*32);
#pragma unroll
            for (int j2 = 0; j2 < 8; ++j2) {
                ulonglong2 w = wr[j2];
                acc[j2*2+0] = ffma2(xx, w.x, acc[j2*2+0]);
                acc[j2*2+1] = ffma2(xx, w.y, acc[j2*2+1]);
            }
        }
    }
    float h2[32];
#pragma unroll
    for (int j = 0; j < 16; ++j) {
        float a, bq; unpack2(acc[j], a, bq);
        h2[2*j]   = fmaxf(a, 0.0f);
        h2[2*j+1] = fmaxf(bq, 0.0f);
    }

    // ---- heads: packed (d0,d1)(d2,c0)(c1,c2) ----
    ull p0 = pack2(cBS[0], cBS[1]);
    ull p1 = pack2(cBS[2], cBS[3]);
    ull p2 = pack2(cBS[4], cBS[5]);
    {
#pragma unroll
        for (int i = 0; i < 32; ++i) {
            ull xx = pack2(h2[i], h2[i]);
            const ulonglong2* wa = (const ulonglong2*)(cWh + i*8);
            ulonglong2 w01 = wa[0];
            ull w2v = ((const ull*)(cWh + i*8))[2];
            p0 = ffma2(xx, w01.x, p0);
            p1 = ffma2(xx, w01.y, p1);
            p2 = ffma2(xx, w2v,   p2);
        }
    }
    float ld0, ld1, ld2, lc0, lc1, lc2;
    unpack2(p0, ld0, ld1);
    unpack2(p1, ld2, lc0);
    unpack2(p2, lc1, lc2);

    // ---- gumbel argmax ----
    float a0 = ld0 + gd0, a1 = ld1 + gd1, a2 = ld2 + gd2;
    int ad = 0; { float best = a0; if (a1 > best) { best = a1; ad = 1; } if (a2 > best) { ad = 2; } }
    float c0 = lc0 + gc0, c1 = lc1 + gc1, c2 = lc2 + gc2;
    int ac = 0; { float best = c0; if (c1 > best) { best = c1; ac = 1; } if (c2 > best) { ac = 2; } }

    // ---- quantizer parameter selection ----
    const bool  fd  = (ad != 0);
    const float sd  = (ad == 2) ? cBS[9]  : cBS[8];
    const float rsd = (ad == 2) ? cBS[13] : cBS[12];
    const float qnd = (ad == 2) ? -8.0f : -2.0f;
    const float qpd = (ad == 2) ?  7.0f :  1.0f;

    const bool  fc  = (ac != 0);
    const float sc  = (ac == 2) ? cBS[11] : cBS[10];
    const float rsc = (ac == 2) ? cBS[15] : cBS[14];
    const float qnc = (ac == 2) ? -8.0f : -2.0f;
    const float qpc = (ac == 2) ?  7.0f :  1.0f;

    // ---- cheap scalar outputs first (stores don't stall) ----
    out[OFF_EBD + gt] = (ad == 1) ? 4.0f  : ((ad == 2) ? 8.0f  : 0.0f);
    out[OFF_EBC + gt] = (ac == 1) ? 32.0f : ((ac == 2) ? 64.0f : 0.0f);
    out[OFF_WD + g3+0] = (ad == 0) ? 1.0f : 0.0f;
    out[OFF_WD + g3+1] = (ad == 1) ? 1.0f : 0.0f;
    out[OFF_WD + g3+2] = (ad == 2) ? 1.0f : 0.0f;
    out[OFF_WC + g3+0] = (ac == 0) ? 1.0f : 0.0f;
    out[OFF_WC + g3+1] = (ac == 1) ? 1.0f : 0.0f;
    out[OFF_WC + g3+2] = (ac == 2) ? 1.0f : 0.0f;

    // ---- v_q ----
    {
        float2 vq;
        vq.x = fd ? lsqv(vv.x, rsd, sd, qnd, qpd) : 0.0f;
        vq.y = fd ? lsqv(vv.y, rsd, sd, qnd, qpd) : 0.0f;
        ((float2*)(out + OFF_VQ))[gt] = vq;
    }

    // ---- H_q: reload H (L2 hit — same lines this thread touched above) ----
    float2* __restrict__ HQ2 = (float2*)(out + OFF_HQ);
#pragma unroll
    for (int n = 0; n < N_; ++n) {
        float2 hv = __ldg(&H2[hbase + n*K_]);
        float2 hq;
        hq.x = fc ? lsqv(hv.x, rsc, sc, qnc, qpc) : 0.0f;
        hq.y = fc ? lsqv(hv.y, rsc, sc, qnc, qpc) : 0.0f;
        HQ2[hbase + n*K_] = hq;
    }
}

// ---------------------------------------------------------------------------
// Launch
// ---------------------------------------------------------------------------
extern "C" void kernel_launch(void* const* d_in, const int* in_sizes, int n_in,
                              void* d_out, int out_size) {
    const float* v   = (const float*)d_in[0];
    const float* H   = (const float*)d_in[1];
    const float* snr = (const float*)d_in[2];
    const float* gd  = (const float*)d_in[3];
    const float* gc  = (const float*)d_in[4];
    const float* W1  = (const float*)d_in[5];
    const float* b1  = (const float*)d_in[6];
    const float* W2  = (const float*)d_in[7];
    const float* b2  = (const float*)d_in[8];
    const float* Wd  = (const float*)d_in[9];
    const float* bd  = (const float*)d_in[10];
    const float* Wc  = (const float*)d_in[11];
    const float* bc  = (const float*)d_in[12];
    const float* s2d = (const float*)d_in[13];
    const float* s4d = (const float*)d_in[14];
    const float* s2c = (const float*)d_in[15];
    const float* s4c = (const float*)d_in[16];
    float* out = (float*)d_out;

    // Raw weight tables -> constant bank (independent of kA)
    cudaMemcpyToSymbolAsync(cW1, W1, 5*32*sizeof(float), 0, cudaMemcpyDeviceToDevice, 0);
    cudaMemcpyToSymbolAsync(cW2, W2, 32*32*sizeof(float), 0, cudaMemcpyDeviceToDevice, 0);
    cudaMemcpyToSymbolAsync(cb1, b1, 32*sizeof(float), 0, cudaMemcpyDeviceToDevice, 0);
    cudaMemcpyToSymbolAsync(cb2, b2, 32*sizeof(float), 0, cudaMemcpyDeviceToDevice, 0);

    // kA computes avg_power AND builds derived tables in block 0
    kA_avg<<<NPART, 256>>>(H, Wd, Wc, bd, bc, s2d, s4d, s2c, s4c);

    // Derived tables -> constant bank (stream-ordered after kA)
    void *p_wh = nullptr, *p_bs = nullptr;
    cudaGetSymbolAddress(&p_wh, g_wh);
    cudaGetSymbolAddress(&p_bs, g_bs);
    cudaMemcpyToSymbolAsync(cWh, p_wh, 32*8*sizeof(float), 0, cudaMemcpyDeviceToDevice, 0);
    cudaMemcpyToSymbolAsync(cBS, p_bs, 16*sizeof(float), 0, cudaMemcpyDeviceToDevice, 0);

    kC_main<<<BLK_/256, 256>>>(v, H, snr, gd, gc, out);
}

// round 7
// speedup vs baseline: 1.5602x; 1.0171x over previous
#include <cuda_runtime.h>

// Problem constants
#define B_   32
#define L_   1024
#define K_   64
#define N_   8
#define BLK_ (B_*L_*K_)          // 2,097,152 samples
#define CHUNK_L 32
#define CHUNKS  (L_/CHUNK_L)
#define NPART   (B_*CHUNKS)

// Output layout (flat f32, reference tuple order)
#define OFF_VQ  0L
#define OFF_HQ  4194304L
#define OFF_EBD 37748736L
#define OFF_EBC 39845888L
#define OFF_WD  41943040L
#define OFF_WC  48234496L

#define RND_MAGIC 12582912.0f    // 1.5 * 2^23 : exact RNE round for |x| <= 8

// Constant table layout (floats)
#define T_W1 0        // 160
#define T_W2 160      // 1024  (byte offset 640, 16B aligned)
#define T_B1 1184     // 32
#define T_B2 1216     // 32
#define T_WH 1248     // 256 (per i: d0 d1 d2 c0 c1 c2 0 0)
#define T_BS 1504     // 16  ([0..5]=bd,bc  [8..15]=s2d s4d s2c s4c r2d r4d r2c r4c)
#define T_TOTAL 1520

typedef unsigned long long ull;

// Scratch (device globals: allocation-free)
__device__ float    g_part[NPART*K_];
__device__ float    g_avg[B_*K_];
__device__ unsigned g_ctr;
__device__ __align__(16) float g_stage[T_TOTAL];

// One constant table (uniform-constant port, not L1)
__constant__ __align__(16) float cT[T_TOTAL];

// ---- packed f32x2 helpers (bitwise-exact dual fp32 ops) ----
__device__ __forceinline__ ull pack2(float x, float y) {
    ull r; asm("mov.b64 %0,{%1,%2};" : "=l"(r) : "f"(x), "f"(y)); return r;
}
__device__ __forceinline__ void unpack2(ull v, float& x, float& y) {
    asm("mov.b64 {%0,%1},%2;" : "=f"(x), "=f"(y) : "l"(v));
}
__device__ __forceinline__ ull ffma2(ull a, ull b, ull c) {
    ull d; asm("fma.rn.f32x2 %0,%1,%2,%3;" : "=l"(d) : "l"(a), "l"(b), "l"(c)); return d;
}
__device__ __forceinline__ ull fmul2(ull a, ull b) {
    ull d; asm("mul.rn.f32x2 %0,%1,%2;" : "=l"(d) : "l"(a), "l"(b)); return d;
}
__device__ __forceinline__ ull fadd2(ull a, ull b) {
    ull d; asm("add.rn.f32x2 %0,%1,%2;" : "=l"(d) : "l"(a), "l"(b)); return d;
}

// ---------------------------------------------------------------------------
// Kernel A: avg_power (ticket last-block finalize) + block 0 stages the full
// constant table into g_stage (one memcpy node follows this kernel).
// ---------------------------------------------------------------------------
__global__ __launch_bounds__(256) void kA_avg(
    const float* __restrict__ H,
    const float* __restrict__ W1, const float* __restrict__ b1,
    const float* __restrict__ W2, const float* __restrict__ b2,
    const float* __restrict__ Wd, const float* __restrict__ Wc,
    const float* __restrict__ bd, const float* __restrict__ bc,
    const float* __restrict__ s2d, const float* __restrict__ s4d,
    const float* __restrict__ s2c, const float* __restrict__ s4c)
{
    const int bx  = blockIdx.x;
    const int tid = threadIdx.x;

    // ---- block 0: stage all tables ----
    if (bx == 0) {
        for (int i = tid; i < 160;  i += 256) g_stage[T_W1 + i] = W1[i];
        for (int i = tid; i < 1024; i += 256) g_stage[T_W2 + i] = W2[i];
        if (tid < 32) {
            g_stage[T_B1 + tid] = b1[tid];
            g_stage[T_B2 + tid] = b2[tid];
            g_stage[T_WH + tid*8+0] = Wd[tid*3+0];
            g_stage[T_WH + tid*8+1] = Wd[tid*3+1];
            g_stage[T_WH + tid*8+2] = Wd[tid*3+2];
            g_stage[T_WH + tid*8+3] = Wc[tid*3+0];
            g_stage[T_WH + tid*8+4] = Wc[tid*3+1];
            g_stage[T_WH + tid*8+5] = Wc[tid*3+2];
            g_stage[T_WH + tid*8+6] = 0.0f;
            g_stage[T_WH + tid*8+7] = 0.0f;
        }
        if (tid == 0) {
            g_stage[T_BS+0] = bd[0]; g_stage[T_BS+1] = bd[1]; g_stage[T_BS+2] = bd[2];
            g_stage[T_BS+3] = bc[0]; g_stage[T_BS+4] = bc[1]; g_stage[T_BS+5] = bc[2];
            g_stage[T_BS+6] = 0.0f;  g_stage[T_BS+7] = 0.0f;
            float a = *s2d, bq = *s4d, c = *s2c, d = *s4c;
            g_stage[T_BS+8]  = a;      g_stage[T_BS+9]  = bq;
            g_stage[T_BS+10] = c;      g_stage[T_BS+11] = d;
            g_stage[T_BS+12] = 1.0f/a; g_stage[T_BS+13] = 1.0f/bq;
            g_stage[T_BS+14] = 1.0f/c; g_stage[T_BS+15] = 1.0f/d;
        }
    }

    const int b     = bx >> 5;
    const int chunk = bx & 31;
    const int k     = tid & 63;
    const int lsub  = tid >> 6;

    const float2* __restrict__ H2 = (const float2*)H;

    float partial = 0.0f;
#pragma unroll
    for (int r = 0; r < CHUNK_L/4; ++r) {
        const int l  = chunk*CHUNK_L + r*4 + lsub;
        const long bl = (long)b*L_ + l;
        float hp = 0.0f;
#pragma unroll
        for (int n = 0; n < N_; ++n) {
            float2 hv = H2[(bl*N_ + n)*K_ + k];
            hp = fmaf(hv.x, hv.x, fmaf(hv.y, hv.y, hp));
        }
        partial += hp;
    }

    __shared__ float sm[256];
    __shared__ unsigned s_ticket;
    sm[tid] = partial;
    __syncthreads();
    if (tid < 64) {
        float s = (sm[tid] + sm[tid+64]) + (sm[tid+128] + sm[tid+192]);
        g_part[bx*64 + tid] = s;
    }
    __threadfence();
    __syncthreads();
    if (tid == 0) s_ticket = atomicAdd(&g_ctr, 1u);
    __syncthreads();

    if (s_ticket == NPART - 1) {
        for (int i = tid; i < B_*K_; i += 256) {
            const int bb = i >> 6;
            const int kk = i & 63;
            float s = 0.0f;
#pragma unroll
            for (int c = 0; c < CHUNKS; ++c)
                s += g_part[(bb*CHUNKS + c)*64 + kk];
            g_avg[i] = s * (1.0f/1024.0f);
        }
        if (tid == 0) g_ctr = 0;
    }
}

// ---------------------------------------------------------------------------
// Packed lsq on a float2: per-lane identical to scalar
//   round(clip(x*rs, qn, qp)) * s   (clamp on alu pipe, rest f32x2 on fma)
// ---------------------------------------------------------------------------
__device__ __forceinline__ ull lsq2(ull xy, ull rs2, ull s2, float qn, float qp) {
    ull t = fmul2(xy, rs2);
    float lo, hi; unpack2(t, lo, hi);
    lo = fminf(fmaxf(lo, qn), qp);         // FMNMX (alu pipe)
    hi = fminf(fmaxf(hi, qn), qp);
    t = pack2(lo, hi);
    const ull m  = pack2(RND_MAGIC, RND_MAGIC);
    const ull nm = pack2(-RND_MAGIC, -RND_MAGIC);
    t = fadd2(t, m);                        // exact RNE round (|t| <= 8)
    t = fadd2(t, nm);
    return fmul2(t, s2);
}

// ---------------------------------------------------------------------------
// Kernel C: MLP (f32x2, constant weights), packed-lsq epilogue.
// ---------------------------------------------------------------------------
__global__ __launch_bounds__(256, 3) void kC_main(
    const float* __restrict__ v,   const float* __restrict__ H,
    const float* __restrict__ snr, const float* __restrict__ gd,
    const float* __restrict__ gc,  float* __restrict__ out)
{
    const int tid = threadIdx.x;
    const int gt  = blockIdx.x*256 + tid;
    const int k   = gt & 63;
    const long bl = gt >> 6;
    const int  b  = gt >> 16;
    const long g3 = (long)gt * 3;

    const float2* __restrict__ H2 = (const float2*)H;
    const long hbase = bl*(N_*K_) + k;

    // ---- h_power: stream H (order preserved; feeds logits -> do not touch) ----
    float hpv = 0.0f;
#pragma unroll
    for (int n = 0; n < N_; ++n) {
        float2 hv = __ldg(&H2[hbase + n*K_]);
        hpv = fmaf(hv.x, hv.x, fmaf(hv.y, hv.y, hpv));
    }

    const float2 vv   = ((const float2*)v)[gt];
    const float  snrv = snr[gt];
    const float  avgv = g_avg[(b<<6) | k];

    float pin[5] = { vv.x, vv.y, snrv, hpv, avgv };

    // ---- layer 1: 5 -> 32 (f32x2) ----
    ull acc[16];
    {
        const ull* bp = (const ull*)(cT + T_B1);
#pragma unroll
        for (int j = 0; j < 16; ++j) acc[j] = bp[j];
#pragma unroll
        for (int i = 0; i < 5; ++i) {
            ull xx = pack2(pin[i], pin[i]);
            const ulonglong2* wr = (const ulonglong2*)(cT + T_W1 + i*32);
#pragma unroll
            for (int j2 = 0; j2 < 8; ++j2) {
                ulonglong2 w = wr[j2];
                acc[j2*2+0] = ffma2(xx, w.x, acc[j2*2+0]);
                acc[j2*2+1] = ffma2(xx, w.y, acc[j2*2+1]);
            }
        }
    }
    float h1[32];
#pragma unroll
    for (int j = 0; j < 16; ++j) {
        float a, bq; unpack2(acc[j], a, bq);
        h1[2*j]   = fmaxf(a, 0.0f);
        h1[2*j+1] = fmaxf(bq, 0.0f);
    }

    // ---- gumbel loads issued here: hidden under layer-2 FMA ----
    const float gd0 = __ldg(&gd[g3+0]), gd1 = __ldg(&gd[g3+1]), gd2 = __ldg(&gd[g3+2]);
    const float gc0 = __ldg(&gc[g3+0]), gc1 = __ldg(&gc[g3+1]), gc2 = __ldg(&gc[g3+2]);

    // ---- layer 2: 32 -> 32 (f32x2) ----
    {
        const ull* bp = (const ull*)(cT + T_B2);
#pragma unroll
        for (int j = 0; j < 16; ++j) acc[j] = bp[j];
#pragma unroll
        for (int i = 0; i < 32; ++i) {
            ull xx = pack2(h1[i], h1[i]);
            const ulonglong2* wr = (const ulonglong2*)(cT + T_W2 + i*32);
#pragma unroll
            for (int j2 = 0; j2 < 8; ++j2) {
                ulonglong2 w = wr[j2];
                acc[j2*2+0] = ffma2(xx, w.x, acc[j2*2+0]);
                acc[j2*2+1] = ffma2(xx, w.y, acc[j2*2+1]);
            }
        }
    }
    float h2[32];
#pragma unroll
    for (int j = 0; j < 16; ++j) {
        float a, bq; unpack2(acc[j], a, bq);
        h2[2*j]   = fmaxf(a, 0.0f);
        h2[2*j+1] = fmaxf(bq, 0.0f);
    }

    // ---- heads: packed (d0,d1)(d2,c0)(c1,c2) ----
    ull p0 = pack2(cT[T_BS+0], cT[T_BS+1]);
    ull p1 = pack2(cT[T_BS+2], cT[T_BS+3]);
    ull p2 = pack2(cT[T_BS+4], cT[T_BS+5]);
    {
#pragma unroll
        for (int i = 0; i < 32; ++i) {
            ull xx = pack2(h2[i], h2[i]);
            const ulonglong2* wa = (const ulonglong2*)(cT + T_WH + i*8);
            ulonglong2 w01 = wa[0];
            ull w2v = ((const ull*)(cT + T_WH + i*8))[2];
            p0 = ffma2(xx, w01.x, p0);
            p1 = ffma2(xx, w01.y, p1);
            p2 = ffma2(xx, w2v,   p2);
        }
    }
    float ld0, ld1, ld2, lc0, lc1, lc2;
    unpack2(p0, ld0, ld1);
    unpack2(p1, ld2, lc0);
    unpack2(p2, lc1, lc2);

    // ---- gumbel argmax ----
    float a0 = ld0 + gd0, a1 = ld1 + gd1, a2 = ld2 + gd2;
    int ad = 0; { float best = a0; if (a1 > best) { best = a1; ad = 1; } if (a2 > best) { ad = 2; } }
    float c0 = lc0 + gc0, c1 = lc1 + gc1, c2 = lc2 + gc2;
    int ac = 0; { float best = c0; if (c1 > best) { best = c1; ac = 1; } if (c2 > best) { ac = 2; } }

    // ---- quantizer parameter selection ----
    const bool  fd  = (ad != 0);
    const float sd  = (ad == 2) ? cT[T_BS+9]  : cT[T_BS+8];
    const float rsd = (ad == 2) ? cT[T_BS+13] : cT[T_BS+12];
    const float qnd = (ad == 2) ? -8.0f : -2.0f;
    const float qpd = (ad == 2) ?  7.0f :  1.0f;

    const bool  fc  = (ac != 0);
    const float sc  = (ac == 2) ? cT[T_BS+11] : cT[T_BS+10];
    const float rsc = (ac == 2) ? cT[T_BS+15] : cT[T_BS+14];
    const float qnc = (ac == 2) ? -8.0f : -2.0f;
    const float qpc = (ac == 2) ?  7.0f :  1.0f;

    // ---- cheap scalar outputs ----
    out[OFF_EBD + gt] = (ad == 1) ? 4.0f  : ((ad == 2) ? 8.0f  : 0.0f);
    out[OFF_EBC + gt] = (ac == 1) ? 32.0f : ((ac == 2) ? 64.0f : 0.0f);
    out[OFF_WD + g3+0] = (ad == 0) ? 1.0f : 0.0f;
    out[OFF_WD + g3+1] = (ad == 1) ? 1.0f : 0.0f;
    out[OFF_WD + g3+2] = (ad == 2) ? 1.0f : 0.0f;
    out[OFF_WC + g3+0] = (ac == 0) ? 1.0f : 0.0f;
    out[OFF_WC + g3+1] = (ac == 1) ? 1.0f : 0.0f;
    out[OFF_WC + g3+2] = (ac == 2) ? 1.0f : 0.0f;

    // ---- v_q (packed lsq; per-lane bitwise identical to scalar) ----
    {
        const ull rsd2 = pack2(rsd, rsd), sd2 = pack2(sd, sd);
        ull q = lsq2(pack2(vv.x, vv.y), rsd2, sd2, qnd, qpd);
        float qx, qy; unpack2(q, qx, qy);
        float2 vq;
        vq.x = fd ? qx : 0.0f;
        vq.y = fd ? qy : 0.0f;
        ((float2*)(out + OFF_VQ))[gt] = vq;
    }

    // ---- H_q: reload H (L2 hit), packed lsq ----
    {
        const ull rsc2 = pack2(rsc, rsc), sc2 = pack2(sc, sc);
        float2* __restrict__ HQ2 = (float2*)(out + OFF_HQ);
#pragma unroll
        for (int n = 0; n < N_; ++n) {
            float2 hv = __ldg(&H2[hbase + n*K_]);
            ull q = lsq2(pack2(hv.x, hv.y), rsc2, sc2, qnc, qpc);
            float qx, qy; unpack2(q, qx, qy);
            float2 hq;
            hq.x = fc ? qx : 0.0f;
            hq.y = fc ? qy : 0.0f;
            HQ2[hbase + n*K_] = hq;
        }
    }
}

// ---------------------------------------------------------------------------
// Launch
// ---------------------------------------------------------------------------
extern "C" void kernel_launch(void* const* d_in, const int* in_sizes, int n_in,
                              void* d_out, int out_size) {
    const float* v   = (const float*)d_in[0];
    const float* H   = (const float*)d_in[1];
    const float* snr = (const float*)d_in[2];
    const float* gd  = (const float*)d_in[3];
    const float* gc  = (const float*)d_in[4];
    const float* W1  = (const float*)d_in[5];
    const float* b1  = (const float*)d_in[6];
    const float* W2  = (const float*)d_in[7];
    const float* b2  = (const float*)d_in[8];
    const float* Wd  = (const float*)d_in[9];
    const float* bd  = (const float*)d_in[10];
    const float* Wc  = (const float*)d_in[11];
    const float* bc  = (const float*)d_in[12];
    const float* s2d = (const float*)d_in[13];
    const float* s4d = (const float*)d_in[14];
    const float* s2c = (const float*)d_in[15];
    const float* s4c = (const float*)d_in[16];
    float* out = (float*)d_out;

    // kA computes avg_power AND stages the full constant table
    kA_avg<<<NPART, 256>>>(H, W1, b1, W2, b2, Wd, Wc, bd, bc, s2d, s4d, s2c, s4c);

    // Single D2D memcpy: staged table -> constant bank
    void* p_stage = nullptr;
    cudaGetSymbolAddress(&p_stage, g_stage);
    cudaMemcpyToSymbolAsync(cT, p_stage, T_TOTAL*sizeof(float), 0,
                            cudaMemcpyDeviceToDevice, 0);

    kC_main<<<BLK_/256, 256>>>(v, H, snr, gd, gc, out);
}